// round 11
// baseline (speedup 1.0000x reference)
#include <cuda_runtime.h>
#include <cuda_fp16.h>
#include <cstdint>
#include <cstddef>

// ---------------- problem constants ----------------
#define BBATCH 32
#define LL   1024
#define DM   512
#define TD   1536          // 3*D
#define NR   1024          // B*C
#define SXN  64
#define SEGN 16
#define NSTEPS 65          // 64 scan steps + 1 decoder step
#define SCAN_CTAS 128
static constexpr size_t SLAB = (size_t)NR * TD;

// ---------------- device scratch ----------------
__device__ float g_seq_last[NR];
__device__ float g_xs[(size_t)NR * LL];
__device__ float g_xt[(size_t)NR * LL];
__device__ __half g_Es[(size_t)NR * SXN * DM];
__device__ __half g_Et[(size_t)NR * SXN * DM];
__device__ __half g_pes[(size_t)NR * DM];
__device__ __half g_pet[(size_t)NR * DM];
__device__ __half g_Wih_s[(size_t)TD * DM];
__device__ __half g_Whh_s[(size_t)TD * DM];
__device__ __half g_Wih_t[(size_t)TD * DM];
__device__ __half g_Whh_t[(size_t)TD * DM];
__device__ __half g_Gi_s[(size_t)NSTEPS * NR * TD];  // fp16 preacts (bih folded)
__device__ __half g_Gi_t[(size_t)NSTEPS * NR * TD];
__device__ __half g_Hbuf[2][2][(size_t)NR * DM];     // [stream][pingpong]
__device__ float g_Hs[(size_t)NR * DM];
__device__ float g_Ht[(size_t)NR * DM];
__device__ unsigned g_flags[128];                    // [grp*8 + db] H-slice ready count

// ---------------- helpers ----------------
__device__ __forceinline__ uint32_t smem_u32(const void* p) {
    uint32_t r;
    asm volatile("{ .reg .u64 t; cvta.to.shared.u64 t, %1; cvt.u32.u64 %0, t; }"
                 : "=r"(r) : "l"(p));
    return r;
}

__device__ __forceinline__ void mma16816(float* c, const uint32_t* a, const uint32_t* b) {
    asm volatile(
        "mma.sync.aligned.m16n8k16.row.col.f32.f16.f16.f32 "
        "{%0,%1,%2,%3}, {%4,%5,%6,%7}, {%8,%9}, {%0,%1,%2,%3};\n"
        : "+f"(c[0]), "+f"(c[1]), "+f"(c[2]), "+f"(c[3])
        : "r"(a[0]), "r"(a[1]), "r"(a[2]), "r"(a[3]), "r"(b[0]), "r"(b[1]));
}

#define SWZ(o) ((o) ^ (((o) >> 3) & 0x70))

// FMA-only 2^v for v in [-31, 31]; err ~1e-7 rel
__device__ __forceinline__ float exp2_fma(float v) {
    float k = v + 12582912.0f;
    float n = k - 12582912.0f;
    float f = v - n;
    int ni = __float_as_int(k) - 0x4B400000;
    float p = 1.54035304e-4f;
    p = fmaf(p, f, 1.33335581e-3f);
    p = fmaf(p, f, 9.61812911e-3f);
    p = fmaf(p, f, 5.55041087e-2f);
    p = fmaf(p, f, 2.40226507e-1f);
    p = fmaf(p, f, 6.93147180e-1f);
    p = fmaf(p, f, 1.0f);
    return __int_as_float(__float_as_int(p) + (ni << 23));
}

// FMA-only reciprocal, 2 Newton steps; err ~1.3e-6 rel
__device__ __forceinline__ float rcp_nr(float d) {
    float x = __int_as_float(0x7EF311C3 - __float_as_int(d));
    x = x * fmaf(-d, x, 2.0f);
    x = x * fmaf(-d, x, 2.0f);
    return x;
}

__device__ __forceinline__ float sigmoid_fma(float x) {
    float v = fmaxf(fminf(-x * 1.44269504f, 30.f), -30.f);
    return rcp_nr(1.0f + exp2_fma(v));
}

__device__ __forceinline__ float tanh_fma(float x) {
    float v = fmaxf(fminf(-x * 2.88539008f, 30.f), -30.f);
    float s = rcp_nr(1.0f + exp2_fma(v));
    return fmaf(2.0f, s, -1.0f);
}

// ---------------- kernel: weight fp32 -> fp16 ----------------
__global__ void cvt_weights(const float* __restrict__ wih_s, const float* __restrict__ whh_s,
                            const float* __restrict__ wih_t, const float* __restrict__ whh_t) {
    int i = blockIdx.x * blockDim.x + threadIdx.x;
    if (i >= TD * DM) return;
    g_Wih_s[i] = __float2half(wih_s[i]);
    g_Whh_s[i] = __float2half(whh_s[i]);
    g_Wih_t[i] = __float2half(wih_t[i]);
    g_Whh_t[i] = __float2half(whh_t[i]);
}

// ---------------- kernel: preprocess (moving mean over CHANNELS) -------------
__global__ void preproc(const float* __restrict__ x) {
    int idx = blockIdx.x * (blockDim.x >> 5) + (threadIdx.x >> 5);  // b*1024 + l
    int lane = threadIdx.x & 31;
    if (idx >= BBATCH * LL) return;
    int b = idx >> 10, l = idx & 1023;
    const float* xb = x + (size_t)b * LL * 32;
    float last = xb[(LL - 1) * 32 + lane];
    float v = xb[(size_t)l * 32 + lane] - last;
    float s = 0.f;
    #pragma unroll
    for (int j = -12; j <= 12; j++) {
        int c = lane + j;
        c = c < 0 ? 0 : (c > 31 ? 31 : c);
        s += __shfl_sync(0xffffffffu, v, c);
    }
    float mean = s * (1.0f / 25.0f);
    int n = (b << 5) + lane;
    g_xt[(size_t)n * LL + l] = mean;
    g_xs[(size_t)n * LL + l] = v - mean;
    if (l == LL - 1) g_seq_last[n] = last;
}

// ---------------- kernel: value embedding (K=16 GEMM + ReLU) ------------------
__global__ void embed(const float* __restrict__ W_emb, const float* __restrict__ b_emb) {
    __shared__ float sWT[SEGN * DM];
    __shared__ float sb[DM];
    const float* src = blockIdx.y ? g_xt : g_xs;
    __half* dst = blockIdx.y ? g_Et : g_Es;
    for (int i = threadIdx.x; i < SEGN * DM; i += blockDim.x) {
        int d = i >> 4, k = i & 15;
        sWT[k * DM + d] = W_emb[i];
    }
    for (int i = threadIdx.x; i < DM; i += blockDim.x) sb[i] = b_emb[i];
    __syncthreads();
    int row0 = blockIdx.x * 8;
    for (int rr = 0; rr < 8; rr++) {
        int r = row0 + rr;
        int sx = r >> 10, n = r & 1023;
        const float* s16 = src + (size_t)n * LL + sx * SEGN;
        float seg[SEGN];
        #pragma unroll
        for (int k = 0; k < SEGN; k++) seg[k] = __ldg(&s16[k]);
        for (int d = threadIdx.x; d < DM; d += blockDim.x) {
            float acc = sb[d];
            #pragma unroll
            for (int k = 0; k < SEGN; k++) acc = fmaf(seg[k], sWT[k * DM + d], acc);
            dst[(size_t)r * DM + d] = __float2half(fmaxf(acc, 0.f));
        }
    }
}

// ---------------- kernel: decoder positional/channel embedding ----------------
__global__ void build_pe(const float* __restrict__ pos_s, const float* __restrict__ ch_s,
                         const float* __restrict__ pos_t, const float* __restrict__ ch_t) {
    int i = blockIdx.x * blockDim.x + threadIdx.x;
    if (i >= NR * DM) return;
    int n = i >> 9, d = i & 511;
    int c = n & 31;
    float vs = (d < 256) ? pos_s[d] : ch_s[c * 256 + (d - 256)];
    float vt = (d < 256) ? pos_t[d] : ch_t[c * 256 + (d - 256)];
    g_pes[i] = __float2half(vs);
    g_pet[i] = __float2half(vt);
}

// ---------------- kernel: init (H ping buffer 0 + flags) ----------------
__global__ void init_state() {
    int i = blockIdx.x * blockDim.x + threadIdx.x;
    if (i < 128) g_flags[i] = 0;
    if (i >= NR * DM) return;
    g_Hbuf[0][0][i] = __float2half(0.f);
    g_Hbuf[1][0][i] = __float2half(0.f);
}

// ---------------- Gi GEMM: C[m][n] = E[m]@Wih[n] + bih[n], fp16 out -----------
#define BM 128
#define BN 128
#define BK 32
#define SST 40

__global__ void __launch_bounds__(256) gemm_gi(int which,
                                               const float* __restrict__ bias0,
                                               const float* __restrict__ bias1) {
    const __half *A, *W;
    __half* C;
    int z = blockIdx.z;
    if (which == 0) {
        A = z ? g_Et : g_Es;
        W = z ? g_Wih_t : g_Wih_s;
        C = z ? g_Gi_t : g_Gi_s;
    } else {
        A = z ? g_pet : g_pes;
        W = z ? g_Wih_t : g_Wih_s;
        C = (z ? g_Gi_t : g_Gi_s) + (size_t)64 * SLAB;
    }
    const float* bias = z ? bias1 : bias0;

    __shared__ __align__(16) __half sA[2][BM][SST];
    __shared__ __align__(16) __half sB[2][BN][SST];

    int tid = threadIdx.x;
    int m0 = blockIdx.y * BM;
    int n0 = blockIdx.x * BN;
    const __half* Ag = A + (size_t)m0 * DM;
    const __half* Wg = W + (size_t)n0 * DM;

    int warp = tid >> 5, lane = tid & 31;
    int wm = warp & 1, wn = warp >> 1;
    int mwarp = wm * 64, nwarp = wn * 32;

    float acc[4][4][4];
    #pragma unroll
    for (int mi = 0; mi < 4; mi++)
        #pragma unroll
        for (int ni = 0; ni < 4; ni++)
            #pragma unroll
            for (int q = 0; q < 4; q++) acc[mi][ni][q] = 0.f;

    const int KT = DM / BK;   // 16

#define LOAD_TILE(buf, k0) do {                                                       \
        _Pragma("unroll")                                                             \
        for (int i_ = 0; i_ < 2; i_++) {                                              \
            int id_ = tid + 256 * i_;                                                 \
            int r_ = id_ >> 2, c8_ = (id_ & 3) * 8;                                   \
            uint32_t s_ = smem_u32(&sA[buf][r_][c8_]);                                \
            const __half* p_ = Ag + (size_t)r_ * DM + (k0) + c8_;                     \
            asm volatile("cp.async.cg.shared.global [%0], [%1], 16;\n" :: "r"(s_), "l"(p_)); \
            s_ = smem_u32(&sB[buf][r_][c8_]);                                         \
            p_ = Wg + (size_t)r_ * DM + (k0) + c8_;                                   \
            asm volatile("cp.async.cg.shared.global [%0], [%1], 16;\n" :: "r"(s_), "l"(p_)); \
        }                                                                             \
        asm volatile("cp.async.commit_group;\n" ::: "memory");                        \
    } while (0)

    LOAD_TILE(0, 0);

    for (int kt = 0; kt < KT; kt++) {
        asm volatile("cp.async.wait_group 0;\n" ::: "memory");
        __syncthreads();
        if (kt + 1 < KT) {
            LOAD_TILE((kt + 1) & 1, (kt + 1) * BK);
        }
        int buf = kt & 1;
        #pragma unroll
        for (int ks = 0; ks < 2; ks++) {
            int k16 = ks * 16;
            uint32_t a[4][4];
            #pragma unroll
            for (int mi = 0; mi < 4; mi++) {
                int row = mwarp + mi * 16 + (lane & 15);
                int col = k16 + (lane >> 4) * 8;
                uint32_t addr = smem_u32(&sA[buf][row][col]);
                asm volatile("ldmatrix.sync.aligned.m8n8.x4.shared.b16 {%0,%1,%2,%3}, [%4];\n"
                             : "=r"(a[mi][0]), "=r"(a[mi][1]), "=r"(a[mi][2]), "=r"(a[mi][3])
                             : "r"(addr));
            }
            uint32_t b[4][2];
            #pragma unroll
            for (int nb = 0; nb < 2; nb++) {
                int g = lane >> 3, rr = lane & 7;
                int nrow = nwarp + nb * 16 + ((g >> 1) << 3) + rr;
                int col = k16 + ((g & 1) << 3);
                uint32_t addr = smem_u32(&sB[buf][nrow][col]);
                uint32_t r0, r1, r2, r3;
                asm volatile("ldmatrix.sync.aligned.m8n8.x4.shared.b16 {%0,%1,%2,%3}, [%4];\n"
                             : "=r"(r0), "=r"(r1), "=r"(r2), "=r"(r3) : "r"(addr));
                b[nb * 2][0] = r0;     b[nb * 2][1] = r1;
                b[nb * 2 + 1][0] = r2; b[nb * 2 + 1][1] = r3;
            }
            #pragma unroll
            for (int mi = 0; mi < 4; mi++)
                #pragma unroll
                for (int ni = 0; ni < 4; ni++)
                    mma16816(acc[mi][ni], a[mi], b[ni]);
        }
    }

    #pragma unroll
    for (int mi = 0; mi < 4; mi++) {
        int row = m0 + mwarp + mi * 16 + (lane >> 2);
        #pragma unroll
        for (int ni = 0; ni < 4; ni++) {
            int col = n0 + nwarp + ni * 8 + (lane & 3) * 2;
            float bv0 = bias[col], bv1 = bias[col + 1];
            *(__half2*)&C[(size_t)row * TD + col] =
                __floats2half2_rn(acc[mi][ni][0] + bv0, acc[mi][ni][1] + bv1);
            *(__half2*)&C[(size_t)(row + 8) * TD + col] =
                __floats2half2_rn(acc[mi][ni][2] + bv0, acc[mi][ni][3] + bv1);
        }
    }
#undef LOAD_TILE
}

// ---------------- persistent fused GRU scan ----------------
// 128 CTAs x 512 threads. CTA (z, mb, db): stream z, m [mb*128,+128),
// d [db*64,+64) over 3 gates. Whh slice chunk-major SW128 in smem (196.6KB),
// A triple-buffered (3x10KB), h in registers. 16 warps: 4m x 4n.
// Sync: per-chunk producer flags. A-chunk c of step t+1 (K cols [c*64,+64))
// is exactly the H slice written by group CTA db=c at step t. Each CTA
// releases flag[grp*8+db] after its gate; consumers acquire flag[c] >= t just
// before loading chunk c (inside the 2-ahead pipeline), so gate skew overlaps
// with GEMM on earlier chunks instead of serializing the whole group.
#define SCAN_SMEM 229440

__global__ void __launch_bounds__(512, 1) scan_kernel(const float* __restrict__ bhh_s,
                                                      const float* __restrict__ bhh_t) {
    extern __shared__ __align__(16) char smraw[];
    uint32_t sbase = smem_u32(smraw);
    uint32_t s0 = (sbase + 1023) & ~1023u;
    const uint32_t sW = s0;                   // 8 chunks x 24576 B (SW128)
    const uint32_t sA = s0 + 196608;          // 3 x 10240 B (128 rows x 80B)
    float* sBias = (float*)(smraw + (s0 + 196608 + 30720 - sbase));

    const int tid = threadIdx.x;
    const int cta = blockIdx.x;
    const int z = cta >> 6;
    const int mb = (cta >> 3) & 7;
    const int db = cta & 7;
    const int m0 = mb * 128;
    const int grp = cta >> 3;
    const int warp = tid >> 5, lane = tid & 31;
    const int wm = warp & 3, wn = warp >> 2;   // 4m x 4n warps: 32m x 48n tiles

    const __half* Whh = z ? g_Whh_t : g_Whh_s;
    const float* bhh = z ? bhh_t : bhh_s;
    const __half* Gi = z ? g_Gi_t : g_Gi_s;
    __half* Hb0 = g_Hbuf[z][0];
    __half* Hb1 = g_Hbuf[z][1];
    float* Hout = z ? g_Ht : g_Hs;
    unsigned* flagbase = &g_flags[grp * 8];

    // ---- resident weight slice, chunk-major SW128
    for (int idx = tid; idx < 12288; idx += 512) {
        int c = idx / 1536;
        int rem = idx - c * 1536;
        int j = rem >> 3, w = rem & 7;
        int jm = j % 48;
        int grow = (jm >> 4) * 512 + db * 64 + (j / 48) * 16 + (jm & 15);
        uint32_t off = (uint32_t)(j * 128 + w * 16);
        uint32_t dst = sW + c * 24576 + SWZ(off);
        const __half* src = Whh + (size_t)grow * 512 + c * 64 + w * 8;
        asm volatile("cp.async.cg.shared.global [%0], [%1], 16;\n" :: "r"(dst), "l"(src));
    }
    asm volatile("cp.async.commit_group;\ncp.async.wait_group 0;\n" ::: "memory");
    if (tid < 192) sBias[tid] = bhh[(tid >> 6) * 512 + db * 64 + (tid & 63)];
    __syncthreads();

    // ---- per-thread bhh preload: bh[gate][ni][pc]
    float bh[3][2][2];
    #pragma unroll
    for (int g = 0; g < 3; g++)
        #pragma unroll
        for (int ni = 0; ni < 2; ni++)
            #pragma unroll
            for (int pc = 0; pc < 2; pc++) {
                int dd = db * 64 + wn * 16 + ni * 8 + (lane & 3) * 2 + pc;
                bh[g][ni][pc] = bhh[g * 512 + dd];
            }

    // ---- register-resident h (16 elements per thread)
    float hreg[2][2][2][2];
    #pragma unroll
    for (int mi = 0; mi < 2; mi++)
        #pragma unroll
        for (int h = 0; h < 2; h++)
            #pragma unroll
            for (int ni = 0; ni < 2; ni++) { hreg[mi][h][ni][0] = 0.f; hreg[mi][h][ni][1] = 0.f; }

#define LOADA(buf, k0) do {                                                          \
        int r_ = tid >> 2, co_ = tid & 3;                                            \
        uint32_t s_ = sA + (buf) * 10240 + r_ * 80 + co_ * 16;                       \
        const __half* p_ = Ag + (size_t)r_ * 512 + (k0) + co_ * 8;                   \
        asm volatile("cp.async.cg.shared.global [%0], [%1], 16;\n" :: "r"(s_), "l"(p_)); \
        asm volatile("cp.async.commit_group;\n" ::: "memory");                       \
    } while (0)

    // flag[c] >= t  <=>  group CTA db=c finished its gate of step t-1
#define WAITF(c_) do {                                                               \
        if ((c_) > chkd) {                                                           \
            unsigned v_;                                                             \
            do {                                                                     \
                asm volatile("ld.acquire.gpu.global.u32 %0, [%1];"                   \
                             : "=r"(v_) : "l"(flagbase + (c_)));                     \
            } while (v_ < (unsigned)t);                                              \
            chkd = (c_);                                                             \
        }                                                                            \
    } while (0)

    for (int t = 0; t < NSTEPS; t++) {
        // ---- prefetch this step's Gi block into L2
        {
            const __half* gib = Gi + (size_t)(t * 1024 + m0) * 1536 + db * 64;
            if (tid < 384) {
                int row = tid & 127, gate = tid >> 7;
                const __half* pf = gib + (size_t)row * 1536 + gate * 512;
                asm volatile("prefetch.global.L2 [%0];" :: "l"(pf));
            }
        }

        float acc[2][6][4];
        #pragma unroll
        for (int mi = 0; mi < 2; mi++)
            #pragma unroll
            for (int ni = 0; ni < 6; ni++)
                #pragma unroll
                for (int q = 0; q < 4; q++) acc[mi][ni][q] = 0.f;

        if (t > 0) {
            int chkd = -1;
            const __half* Ag = ((t & 1) ? Hb1 : Hb0) + (size_t)m0 * 512;
            WAITF(0);
            LOADA(0, 0);
            LOADA(1, 32);
            for (int kt = 0; kt < 16; kt++) {
                if (kt < 15) asm volatile("cp.async.wait_group 1;\n" ::: "memory");
                else         asm volatile("cp.async.wait_group 0;\n" ::: "memory");
                __syncthreads();
                if (kt + 2 < 16) {
                    WAITF((kt + 2) >> 1);
                    LOADA((kt + 2) % 3, (kt + 2) * 32);
                }
                int buf = kt % 3;
                #pragma unroll
                for (int ks = 0; ks < 2; ks++) {
                    uint32_t a[2][4];
                    #pragma unroll
                    for (int mi = 0; mi < 2; mi++) {
                        int row = wm * 32 + mi * 16 + (lane & 15);
                        uint32_t addr = sA + buf * 10240 + row * 80
                                        + (ks * 16 + (lane >> 4) * 8) * 2;
                        asm volatile("ldmatrix.sync.aligned.m8n8.x4.shared.b16 {%0,%1,%2,%3}, [%4];\n"
                                     : "=r"(a[mi][0]), "=r"(a[mi][1]), "=r"(a[mi][2]), "=r"(a[mi][3])
                                     : "r"(addr));
                    }
                    uint32_t b[6][2];
                    #pragma unroll
                    for (int nb = 0; nb < 3; nb++) {
                        int g = lane >> 3, rr = lane & 7;
                        int j = wn * 48 + nb * 16 + ((g >> 1) << 3) + rr;
                        uint32_t off = (uint32_t)(j * 128 + (kt & 1) * 64 + ks * 32 + (g & 1) * 16);
                        uint32_t addr = sW + (kt >> 1) * 24576 + SWZ(off);
                        uint32_t r0, r1, r2, r3;
                        asm volatile("ldmatrix.sync.aligned.m8n8.x4.shared.b16 {%0,%1,%2,%3}, [%4];\n"
                                     : "=r"(r0), "=r"(r1), "=r"(r2), "=r"(r3) : "r"(addr));
                        b[nb * 2][0] = r0;     b[nb * 2][1] = r1;
                        b[nb * 2 + 1][0] = r2; b[nb * 2 + 1][1] = r3;
                    }
                    #pragma unroll
                    for (int mi = 0; mi < 2; mi++)
                        #pragma unroll
                        for (int ni = 0; ni < 6; ni++)
                            mma16816(acc[mi][ni], a[mi], b[ni]);
                }
            }
        }

        // ---- gate phase (registers)
        {
            const __half* gib = Gi + (size_t)(t * 1024 + m0) * 1536;
            __half* Hw = ((t + 1) & 1) ? Hb1 : Hb0;
            int ddb = db * 64 + wn * 16 + (lane & 3) * 2;
            #pragma unroll
            for (int mi = 0; mi < 2; mi++) {
                #pragma unroll
                for (int h = 0; h < 2; h++) {
                    int rl = wm * 32 + mi * 16 + (lane >> 2) + h * 8;
                    #pragma unroll
                    for (int ni = 0; ni < 2; ni++) {
                        int dd = ddb + ni * 8;
                        const __half* gp = gib + (size_t)rl * 1536 + dd;
                        __half2 gr2 = *(const __half2*)(gp);
                        __half2 gz2 = *(const __half2*)(gp + 512);
                        __half2 gn2 = *(const __half2*)(gp + 1024);
                        float hn01[2];
                        #pragma unroll
                        for (int pc = 0; pc < 2; pc++) {
                            float ir = pc ? __high2float(gr2) : __low2float(gr2);
                            float iz = pc ? __high2float(gz2) : __low2float(gz2);
                            float in_ = pc ? __high2float(gn2) : __low2float(gn2);
                            float hr = acc[mi][ni][h * 2 + pc] + bh[0][ni][pc];
                            float hz = acc[mi][ni + 2][h * 2 + pc] + bh[1][ni][pc];
                            float hn = acc[mi][ni + 4][h * 2 + pc] + bh[2][ni][pc];
                            float r = sigmoid_fma(ir + hr);
                            float zz = sigmoid_fma(iz + hz);
                            float nn = tanh_fma(fmaf(r, hn, in_));
                            float hold = hreg[mi][h][ni][pc];
                            float hnew = fmaf(zz, hold - nn, nn);
                            hreg[mi][h][ni][pc] = hnew;
                            hn01[pc] = hnew;
                        }
                        *(__half2*)&Hw[(size_t)(m0 + rl) * 512 + dd] =
                            __floats2half2_rn(hn01[0], hn01[1]);
                        if (t == NSTEPS - 1) {
                            *(float2*)&Hout[(size_t)(m0 + rl) * 512 + dd] =
                                make_float2(hn01[0], hn01[1]);
                        }
                    }
                }
            }
        }

        // ---- publish own H slice (release, cumulative over __syncthreads)
        __syncthreads();
        if (tid == 0) {
            asm volatile("red.release.gpu.global.add.u32 [%0], %1;"
                         :: "l"(flagbase + db), "r"(1u) : "memory");
        }
    }
#undef LOADA
#undef WAITF
}

// ---------------- kernel: prediction head + seq_last add ----------------
__global__ void head_kernel(const float* __restrict__ Wps, const float* __restrict__ bps,
                            const float* __restrict__ Wpt, const float* __restrict__ bpt,
                            float* __restrict__ out) {
    int n = blockIdx.x;
    int lane = threadIdx.x & 31, w = threadIdx.x >> 5;   // 4 warps
    const float* hs = g_Hs + (size_t)n * DM;
    const float* ht = g_Ht + (size_t)n * DM;
    #pragma unroll
    for (int pp = 0; pp < 4; pp++) {
        int p = w * 4 + pp;
        float acc = 0.f;
        for (int k = lane; k < DM; k += 32)
            acc = fmaf(hs[k], Wps[p * DM + k], fmaf(ht[k], Wpt[p * DM + k], acc));
        #pragma unroll
        for (int o = 16; o; o >>= 1) acc += __shfl_xor_sync(0xffffffffu, acc, o);
        if (lane == 0) {
            int b = n >> 5, c = n & 31;
            out[b * (16 * 32) + p * 32 + c] = acc + bps[p] + bpt[p] + g_seq_last[n];
        }
    }
}

// ---------------- launch ----------------
extern "C" void kernel_launch(void* const* d_in, const int* in_sizes, int n_in,
                              void* d_out, int out_size) {
    const float* x     = (const float*)d_in[0];
    const float* W_emb = (const float*)d_in[1];
    const float* b_emb = (const float*)d_in[2];
    const float* Wih_s = (const float*)d_in[3];
    const float* Whh_s = (const float*)d_in[4];
    const float* bih_s = (const float*)d_in[5];
    const float* bhh_s = (const float*)d_in[6];
    const float* Wih_t = (const float*)d_in[7];
    const float* Whh_t = (const float*)d_in[8];
    const float* bih_t = (const float*)d_in[9];
    const float* bhh_t = (const float*)d_in[10];
    const float* pos_s = (const float*)d_in[11];
    const float* ch_s  = (const float*)d_in[12];
    const float* pos_t = (const float*)d_in[13];
    const float* ch_t  = (const float*)d_in[14];
    const float* Wps   = (const float*)d_in[15];
    const float* bps   = (const float*)d_in[16];
    const float* Wpt   = (const float*)d_in[17];
    const float* bpt   = (const float*)d_in[18];
    float* out = (float*)d_out;

    cudaFuncSetAttribute(scan_kernel, cudaFuncAttributeMaxDynamicSharedMemorySize, SCAN_SMEM);

    cvt_weights<<<(TD * DM + 255) / 256, 256>>>(Wih_s, Whh_s, Wih_t, Whh_t);
    preproc<<<(BBATCH * LL) / 8, 256>>>(x);
    embed<<<dim3((NR * SXN) / 8, 2), 256>>>(W_emb, b_emb);
    build_pe<<<(NR * DM + 255) / 256, 256>>>(pos_s, ch_s, pos_t, ch_t);
    init_state<<<(NR * DM + 255) / 256, 256>>>();

    // Gi for all 64 scan steps (M = 65536) and decoder step (M = 1024)
    gemm_gi<<<dim3(TD / BN, (NR * SXN) / BM, 2), 256>>>(0, bih_s, bih_t);
    gemm_gi<<<dim3(TD / BN, NR / BM, 2), 256>>>(1, bih_s, bih_t);

    // fused persistent scan: 64 steps + decoder step, one launch
    scan_kernel<<<SCAN_CTAS, 512, SCAN_SMEM>>>(bhh_s, bhh_t);

    head_kernel<<<NR, 128>>>(Wps, bps, Wpt, bpt, out);
}

// round 16
// speedup vs baseline: 1.4935x; 1.4935x over previous
#include <cuda_runtime.h>
#include <cuda_fp16.h>
#include <cstdint>
#include <cstddef>

// ---------------- problem constants ----------------
#define BBATCH 32
#define LL   1024
#define DM   512
#define TD   1536          // 3*D
#define NR   1024          // B*C
#define SXN  64
#define SEGN 16
#define NSTEPS 65          // 64 scan steps + 1 decoder step
#define SCAN_CTAS 128
static constexpr size_t SLAB = (size_t)NR * TD;

// ---------------- device scratch ----------------
__device__ float g_seq_last[NR];
__device__ float g_xs[(size_t)NR * LL];
__device__ float g_xt[(size_t)NR * LL];
__device__ __half g_Es[(size_t)NR * SXN * DM];
__device__ __half g_Et[(size_t)NR * SXN * DM];
__device__ __half g_pes[(size_t)NR * DM];
__device__ __half g_pet[(size_t)NR * DM];
__device__ __half g_Wih_s[(size_t)TD * DM];
__device__ __half g_Whh_s[(size_t)TD * DM];
__device__ __half g_Wih_t[(size_t)TD * DM];
__device__ __half g_Whh_t[(size_t)TD * DM];
__device__ __half g_Gi_s[(size_t)NSTEPS * NR * TD];  // fp16 preacts (bih folded)
__device__ __half g_Gi_t[(size_t)NSTEPS * NR * TD];
__device__ __half g_Hbuf[2][2][(size_t)NR * DM];     // [stream][pingpong]
__device__ float g_Hs[(size_t)NR * DM];
__device__ float g_Ht[(size_t)NR * DM];
__device__ unsigned g_flags[128];                    // [grp*8 + db] H-slice ready count

// ---------------- helpers ----------------
__device__ __forceinline__ uint32_t smem_u32(const void* p) {
    uint32_t r;
    asm volatile("{ .reg .u64 t; cvta.to.shared.u64 t, %1; cvt.u32.u64 %0, t; }"
                 : "=r"(r) : "l"(p));
    return r;
}

__device__ __forceinline__ void mma16816(float* c, const uint32_t* a, const uint32_t* b) {
    asm volatile(
        "mma.sync.aligned.m16n8k16.row.col.f32.f16.f16.f32 "
        "{%0,%1,%2,%3}, {%4,%5,%6,%7}, {%8,%9}, {%0,%1,%2,%3};\n"
        : "+f"(c[0]), "+f"(c[1]), "+f"(c[2]), "+f"(c[3])
        : "r"(a[0]), "r"(a[1]), "r"(a[2]), "r"(a[3]), "r"(b[0]), "r"(b[1]));
}

#define SWZ(o) ((o) ^ (((o) >> 3) & 0x70))

// FMA-only 2^v for v in [-31, 31]; err ~1e-7 rel
__device__ __forceinline__ float exp2_fma(float v) {
    float k = v + 12582912.0f;
    float n = k - 12582912.0f;
    float f = v - n;
    int ni = __float_as_int(k) - 0x4B400000;
    float p = 1.54035304e-4f;
    p = fmaf(p, f, 1.33335581e-3f);
    p = fmaf(p, f, 9.61812911e-3f);
    p = fmaf(p, f, 5.55041087e-2f);
    p = fmaf(p, f, 2.40226507e-1f);
    p = fmaf(p, f, 6.93147180e-1f);
    p = fmaf(p, f, 1.0f);
    return __int_as_float(__float_as_int(p) + (ni << 23));
}

// FMA-only reciprocal, 2 Newton steps; err ~1.3e-6 rel
__device__ __forceinline__ float rcp_nr(float d) {
    float x = __int_as_float(0x7EF311C3 - __float_as_int(d));
    x = x * fmaf(-d, x, 2.0f);
    x = x * fmaf(-d, x, 2.0f);
    return x;
}

__device__ __forceinline__ float sigmoid_fma(float x) {
    float v = fmaxf(fminf(-x * 1.44269504f, 30.f), -30.f);
    return rcp_nr(1.0f + exp2_fma(v));
}

__device__ __forceinline__ float tanh_fma(float x) {
    float v = fmaxf(fminf(-x * 2.88539008f, 30.f), -30.f);
    float s = rcp_nr(1.0f + exp2_fma(v));
    return fmaf(2.0f, s, -1.0f);
}

// ---------------- kernel: weight fp32 -> fp16 ----------------
__global__ void cvt_weights(const float* __restrict__ wih_s, const float* __restrict__ whh_s,
                            const float* __restrict__ wih_t, const float* __restrict__ whh_t) {
    int i = blockIdx.x * blockDim.x + threadIdx.x;
    if (i >= TD * DM) return;
    g_Wih_s[i] = __float2half(wih_s[i]);
    g_Whh_s[i] = __float2half(whh_s[i]);
    g_Wih_t[i] = __float2half(wih_t[i]);
    g_Whh_t[i] = __float2half(whh_t[i]);
}

// ---------------- kernel: preprocess (moving mean over CHANNELS) -------------
__global__ void preproc(const float* __restrict__ x) {
    int idx = blockIdx.x * (blockDim.x >> 5) + (threadIdx.x >> 5);  // b*1024 + l
    int lane = threadIdx.x & 31;
    if (idx >= BBATCH * LL) return;
    int b = idx >> 10, l = idx & 1023;
    const float* xb = x + (size_t)b * LL * 32;
    float last = xb[(LL - 1) * 32 + lane];
    float v = xb[(size_t)l * 32 + lane] - last;
    float s = 0.f;
    #pragma unroll
    for (int j = -12; j <= 12; j++) {
        int c = lane + j;
        c = c < 0 ? 0 : (c > 31 ? 31 : c);
        s += __shfl_sync(0xffffffffu, v, c);
    }
    float mean = s * (1.0f / 25.0f);
    int n = (b << 5) + lane;
    g_xt[(size_t)n * LL + l] = mean;
    g_xs[(size_t)n * LL + l] = v - mean;
    if (l == LL - 1) g_seq_last[n] = last;
}

// ---------------- kernel: value embedding (K=16 GEMM + ReLU) ------------------
__global__ void embed(const float* __restrict__ W_emb, const float* __restrict__ b_emb) {
    __shared__ float sWT[SEGN * DM];
    __shared__ float sb[DM];
    const float* src = blockIdx.y ? g_xt : g_xs;
    __half* dst = blockIdx.y ? g_Et : g_Es;
    for (int i = threadIdx.x; i < SEGN * DM; i += blockDim.x) {
        int d = i >> 4, k = i & 15;
        sWT[k * DM + d] = W_emb[i];
    }
    for (int i = threadIdx.x; i < DM; i += blockDim.x) sb[i] = b_emb[i];
    __syncthreads();
    int row0 = blockIdx.x * 8;
    for (int rr = 0; rr < 8; rr++) {
        int r = row0 + rr;
        int sx = r >> 10, n = r & 1023;
        const float* s16 = src + (size_t)n * LL + sx * SEGN;
        float seg[SEGN];
        #pragma unroll
        for (int k = 0; k < SEGN; k++) seg[k] = __ldg(&s16[k]);
        for (int d = threadIdx.x; d < DM; d += blockDim.x) {
            float acc = sb[d];
            #pragma unroll
            for (int k = 0; k < SEGN; k++) acc = fmaf(seg[k], sWT[k * DM + d], acc);
            dst[(size_t)r * DM + d] = __float2half(fmaxf(acc, 0.f));
        }
    }
}

// ---------------- kernel: decoder positional/channel embedding ----------------
__global__ void build_pe(const float* __restrict__ pos_s, const float* __restrict__ ch_s,
                         const float* __restrict__ pos_t, const float* __restrict__ ch_t) {
    int i = blockIdx.x * blockDim.x + threadIdx.x;
    if (i >= NR * DM) return;
    int n = i >> 9, d = i & 511;
    int c = n & 31;
    float vs = (d < 256) ? pos_s[d] : ch_s[c * 256 + (d - 256)];
    float vt = (d < 256) ? pos_t[d] : ch_t[c * 256 + (d - 256)];
    g_pes[i] = __float2half(vs);
    g_pet[i] = __float2half(vt);
}

// ---------------- kernel: init (H ping buffer 0 + flags) ----------------
__global__ void init_state() {
    int i = blockIdx.x * blockDim.x + threadIdx.x;
    if (i < 128) g_flags[i] = 0;
    if (i >= NR * DM) return;
    g_Hbuf[0][0][i] = __float2half(0.f);
    g_Hbuf[1][0][i] = __float2half(0.f);
}

// ---------------- Gi GEMM: C[m][n] = E[m]@Wih[n] + bih[n], fp16 out -----------
#define BM 128
#define BN 128
#define BK 32
#define SST 40

__global__ void __launch_bounds__(256) gemm_gi(int which,
                                               const float* __restrict__ bias0,
                                               const float* __restrict__ bias1) {
    const __half *A, *W;
    __half* C;
    int z = blockIdx.z;
    if (which == 0) {
        A = z ? g_Et : g_Es;
        W = z ? g_Wih_t : g_Wih_s;
        C = z ? g_Gi_t : g_Gi_s;
    } else {
        A = z ? g_pet : g_pes;
        W = z ? g_Wih_t : g_Wih_s;
        C = (z ? g_Gi_t : g_Gi_s) + (size_t)64 * SLAB;
    }
    const float* bias = z ? bias1 : bias0;

    __shared__ __align__(16) __half sA[2][BM][SST];
    __shared__ __align__(16) __half sB[2][BN][SST];

    int tid = threadIdx.x;
    int m0 = blockIdx.y * BM;
    int n0 = blockIdx.x * BN;
    const __half* Ag = A + (size_t)m0 * DM;
    const __half* Wg = W + (size_t)n0 * DM;

    int warp = tid >> 5, lane = tid & 31;
    int wm = warp & 1, wn = warp >> 1;
    int mwarp = wm * 64, nwarp = wn * 32;

    float acc[4][4][4];
    #pragma unroll
    for (int mi = 0; mi < 4; mi++)
        #pragma unroll
        for (int ni = 0; ni < 4; ni++)
            #pragma unroll
            for (int q = 0; q < 4; q++) acc[mi][ni][q] = 0.f;

    const int KT = DM / BK;   // 16

#define LOAD_TILE(buf, k0) do {                                                       \
        _Pragma("unroll")                                                             \
        for (int i_ = 0; i_ < 2; i_++) {                                              \
            int id_ = tid + 256 * i_;                                                 \
            int r_ = id_ >> 2, c8_ = (id_ & 3) * 8;                                   \
            uint32_t s_ = smem_u32(&sA[buf][r_][c8_]);                                \
            const __half* p_ = Ag + (size_t)r_ * DM + (k0) + c8_;                     \
            asm volatile("cp.async.cg.shared.global [%0], [%1], 16;\n" :: "r"(s_), "l"(p_)); \
            s_ = smem_u32(&sB[buf][r_][c8_]);                                         \
            p_ = Wg + (size_t)r_ * DM + (k0) + c8_;                                   \
            asm volatile("cp.async.cg.shared.global [%0], [%1], 16;\n" :: "r"(s_), "l"(p_)); \
        }                                                                             \
        asm volatile("cp.async.commit_group;\n" ::: "memory");                        \
    } while (0)

    LOAD_TILE(0, 0);

    for (int kt = 0; kt < KT; kt++) {
        asm volatile("cp.async.wait_group 0;\n" ::: "memory");
        __syncthreads();
        if (kt + 1 < KT) {
            LOAD_TILE((kt + 1) & 1, (kt + 1) * BK);
        }
        int buf = kt & 1;
        #pragma unroll
        for (int ks = 0; ks < 2; ks++) {
            int k16 = ks * 16;
            uint32_t a[4][4];
            #pragma unroll
            for (int mi = 0; mi < 4; mi++) {
                int row = mwarp + mi * 16 + (lane & 15);
                int col = k16 + (lane >> 4) * 8;
                uint32_t addr = smem_u32(&sA[buf][row][col]);
                asm volatile("ldmatrix.sync.aligned.m8n8.x4.shared.b16 {%0,%1,%2,%3}, [%4];\n"
                             : "=r"(a[mi][0]), "=r"(a[mi][1]), "=r"(a[mi][2]), "=r"(a[mi][3])
                             : "r"(addr));
            }
            uint32_t b[4][2];
            #pragma unroll
            for (int nb = 0; nb < 2; nb++) {
                int g = lane >> 3, rr = lane & 7;
                int nrow = nwarp + nb * 16 + ((g >> 1) << 3) + rr;
                int col = k16 + ((g & 1) << 3);
                uint32_t addr = smem_u32(&sB[buf][nrow][col]);
                uint32_t r0, r1, r2, r3;
                asm volatile("ldmatrix.sync.aligned.m8n8.x4.shared.b16 {%0,%1,%2,%3}, [%4];\n"
                             : "=r"(r0), "=r"(r1), "=r"(r2), "=r"(r3) : "r"(addr));
                b[nb * 2][0] = r0;     b[nb * 2][1] = r1;
                b[nb * 2 + 1][0] = r2; b[nb * 2 + 1][1] = r3;
            }
            #pragma unroll
            for (int mi = 0; mi < 4; mi++)
                #pragma unroll
                for (int ni = 0; ni < 4; ni++)
                    mma16816(acc[mi][ni], a[mi], b[ni]);
        }
    }

    #pragma unroll
    for (int mi = 0; mi < 4; mi++) {
        int row = m0 + mwarp + mi * 16 + (lane >> 2);
        #pragma unroll
        for (int ni = 0; ni < 4; ni++) {
            int col = n0 + nwarp + ni * 8 + (lane & 3) * 2;
            float bv0 = bias[col], bv1 = bias[col + 1];
            *(__half2*)&C[(size_t)row * TD + col] =
                __floats2half2_rn(acc[mi][ni][0] + bv0, acc[mi][ni][1] + bv1);
            *(__half2*)&C[(size_t)(row + 8) * TD + col] =
                __floats2half2_rn(acc[mi][ni][2] + bv0, acc[mi][ni][3] + bv1);
        }
    }
#undef LOAD_TILE
}

// ---------------- persistent fused GRU scan ----------------
// 128 CTAs x 512 threads. CTA (z, mb, db): stream z, m [mb*128,+128),
// d [db*64,+64) over 3 gates. Whh slice chunk-major SW128 in smem (196.6KB),
// A triple-buffered (3x10KB), h in registers. 16 warps: 4m x 4n.
// Sync: per-chunk producer flags, but polled by LANE 0 of each warp only,
// with nanosleep backoff (R11's all-thread acquire-poll storm saturated the
// L2 slice holding the flags and slowed the producers themselves).
#define SCAN_SMEM 229440

__global__ void __launch_bounds__(512, 1) scan_kernel(const float* __restrict__ bhh_s,
                                                      const float* __restrict__ bhh_t) {
    extern __shared__ __align__(16) char smraw[];
    uint32_t sbase = smem_u32(smraw);
    uint32_t s0 = (sbase + 1023) & ~1023u;
    const uint32_t sW = s0;                   // 8 chunks x 24576 B (SW128)
    const uint32_t sA = s0 + 196608;          // 3 x 10240 B (128 rows x 80B)
    float* sBias = (float*)(smraw + (s0 + 196608 + 30720 - sbase));

    const int tid = threadIdx.x;
    const int cta = blockIdx.x;
    const int z = cta >> 6;
    const int mb = (cta >> 3) & 7;
    const int db = cta & 7;
    const int m0 = mb * 128;
    const int grp = cta >> 3;
    const int warp = tid >> 5, lane = tid & 31;
    const int wm = warp & 3, wn = warp >> 2;   // 4m x 4n warps: 32m x 48n tiles

    const __half* Whh = z ? g_Whh_t : g_Whh_s;
    const float* bhh = z ? bhh_t : bhh_s;
    const __half* Gi = z ? g_Gi_t : g_Gi_s;
    __half* Hb0 = g_Hbuf[z][0];
    __half* Hb1 = g_Hbuf[z][1];
    float* Hout = z ? g_Ht : g_Hs;
    unsigned* flagbase = &g_flags[grp * 8];

    // ---- resident weight slice, chunk-major SW128
    for (int idx = tid; idx < 12288; idx += 512) {
        int c = idx / 1536;
        int rem = idx - c * 1536;
        int j = rem >> 3, w = rem & 7;
        int jm = j % 48;
        int grow = (jm >> 4) * 512 + db * 64 + (j / 48) * 16 + (jm & 15);
        uint32_t off = (uint32_t)(j * 128 + w * 16);
        uint32_t dst = sW + c * 24576 + SWZ(off);
        const __half* src = Whh + (size_t)grow * 512 + c * 64 + w * 8;
        asm volatile("cp.async.cg.shared.global [%0], [%1], 16;\n" :: "r"(dst), "l"(src));
    }
    asm volatile("cp.async.commit_group;\ncp.async.wait_group 0;\n" ::: "memory");
    if (tid < 192) sBias[tid] = bhh[(tid >> 6) * 512 + db * 64 + (tid & 63)];
    __syncthreads();

    // ---- per-thread bhh preload: bh[gate][ni][pc]
    float bh[3][2][2];
    #pragma unroll
    for (int g = 0; g < 3; g++)
        #pragma unroll
        for (int ni = 0; ni < 2; ni++)
            #pragma unroll
            for (int pc = 0; pc < 2; pc++) {
                int dd = db * 64 + wn * 16 + ni * 8 + (lane & 3) * 2 + pc;
                bh[g][ni][pc] = bhh[g * 512 + dd];
            }

    // ---- register-resident h (16 elements per thread)
    float hreg[2][2][2][2];
    #pragma unroll
    for (int mi = 0; mi < 2; mi++)
        #pragma unroll
        for (int h = 0; h < 2; h++)
            #pragma unroll
            for (int ni = 0; ni < 2; ni++) { hreg[mi][h][ni][0] = 0.f; hreg[mi][h][ni][1] = 0.f; }

#define LOADA(buf, k0) do {                                                          \
        int r_ = tid >> 2, co_ = tid & 3;                                            \
        uint32_t s_ = sA + (buf) * 10240 + r_ * 80 + co_ * 16;                       \
        const __half* p_ = Ag + (size_t)r_ * 512 + (k0) + co_ * 8;                   \
        asm volatile("cp.async.cg.shared.global [%0], [%1], 16;\n" :: "r"(s_), "l"(p_)); \
        asm volatile("cp.async.commit_group;\n" ::: "memory");                       \
    } while (0)

    // flag[c] >= t  <=>  group CTA db=c finished its gate of step t-1.
    // Only lane 0 of each warp polls (nanosleep backoff); __syncwarp releases
    // the warp. Uniform control flow: every thread reaches each WAITF site.
#define WAITF(c_) do {                                                               \
        if ((c_) > chkd) {                                                           \
            if ((tid & 31) == 0) {                                                   \
                unsigned v_;                                                         \
                while (true) {                                                       \
                    asm volatile("ld.acquire.gpu.global.u32 %0, [%1];"               \
                                 : "=r"(v_) : "l"(flagbase + (c_)));                 \
                    if (v_ >= (unsigned)t) break;                                    \
                    __nanosleep(128);                                                \
                }                                                                    \
            }                                                                        \
            __syncwarp();                                                            \
            chkd = (c_);                                                             \
        }                                                                            \
    } while (0)

    for (int t = 0; t < NSTEPS; t++) {
        // ---- prefetch this step's Gi block into L2
        {
            const __half* gib = Gi + (size_t)(t * 1024 + m0) * 1536 + db * 64;
            if (tid < 384) {
                int row = tid & 127, gate = tid >> 7;
                const __half* pf = gib + (size_t)row * 1536 + gate * 512;
                asm volatile("prefetch.global.L2 [%0];" :: "l"(pf));
            }
        }

        float acc[2][6][4];
        #pragma unroll
        for (int mi = 0; mi < 2; mi++)
            #pragma unroll
            for (int ni = 0; ni < 6; ni++)
                #pragma unroll
                for (int q = 0; q < 4; q++) acc[mi][ni][q] = 0.f;

        if (t > 0) {
            int chkd = -1;
            const __half* Ag = ((t & 1) ? Hb1 : Hb0) + (size_t)m0 * 512;
            WAITF(0);
            LOADA(0, 0);
            LOADA(1, 32);
            for (int kt = 0; kt < 16; kt++) {
                if (kt < 15) asm volatile("cp.async.wait_group 1;\n" ::: "memory");
                else         asm volatile("cp.async.wait_group 0;\n" ::: "memory");
                __syncthreads();
                if (kt + 2 < 16) {
                    WAITF((kt + 2) >> 1);
                    LOADA((kt + 2) % 3, (kt + 2) * 32);
                }
                int buf = kt % 3;
                #pragma unroll
                for (int ks = 0; ks < 2; ks++) {
                    uint32_t a[2][4];
                    #pragma unroll
                    for (int mi = 0; mi < 2; mi++) {
                        int row = wm * 32 + mi * 16 + (lane & 15);
                        uint32_t addr = sA + buf * 10240 + row * 80
                                        + (ks * 16 + (lane >> 4) * 8) * 2;
                        asm volatile("ldmatrix.sync.aligned.m8n8.x4.shared.b16 {%0,%1,%2,%3}, [%4];\n"
                                     : "=r"(a[mi][0]), "=r"(a[mi][1]), "=r"(a[mi][2]), "=r"(a[mi][3])
                                     : "r"(addr));
                    }
                    uint32_t b[6][2];
                    #pragma unroll
                    for (int nb = 0; nb < 3; nb++) {
                        int g = lane >> 3, rr = lane & 7;
                        int j = wn * 48 + nb * 16 + ((g >> 1) << 3) + rr;
                        uint32_t off = (uint32_t)(j * 128 + (kt & 1) * 64 + ks * 32 + (g & 1) * 16);
                        uint32_t addr = sW + (kt >> 1) * 24576 + SWZ(off);
                        uint32_t r0, r1, r2, r3;
                        asm volatile("ldmatrix.sync.aligned.m8n8.x4.shared.b16 {%0,%1,%2,%3}, [%4];\n"
                                     : "=r"(r0), "=r"(r1), "=r"(r2), "=r"(r3) : "r"(addr));
                        b[nb * 2][0] = r0;     b[nb * 2][1] = r1;
                        b[nb * 2 + 1][0] = r2; b[nb * 2 + 1][1] = r3;
                    }
                    #pragma unroll
                    for (int mi = 0; mi < 2; mi++)
                        #pragma unroll
                        for (int ni = 0; ni < 6; ni++)
                            mma16816(acc[mi][ni], a[mi], b[ni]);
                }
            }
        }

        // ---- gate phase (registers)
        {
            const __half* gib = Gi + (size_t)(t * 1024 + m0) * 1536;
            __half* Hw = ((t + 1) & 1) ? Hb1 : Hb0;
            int ddb = db * 64 + wn * 16 + (lane & 3) * 2;
            #pragma unroll
            for (int mi = 0; mi < 2; mi++) {
                #pragma unroll
                for (int h = 0; h < 2; h++) {
                    int rl = wm * 32 + mi * 16 + (lane >> 2) + h * 8;
                    #pragma unroll
                    for (int ni = 0; ni < 2; ni++) {
                        int dd = ddb + ni * 8;
                        const __half* gp = gib + (size_t)rl * 1536 + dd;
                        __half2 gr2 = *(const __half2*)(gp);
                        __half2 gz2 = *(const __half2*)(gp + 512);
                        __half2 gn2 = *(const __half2*)(gp + 1024);
                        float hn01[2];
                        #pragma unroll
                        for (int pc = 0; pc < 2; pc++) {
                            float ir = pc ? __high2float(gr2) : __low2float(gr2);
                            float iz = pc ? __high2float(gz2) : __low2float(gz2);
                            float in_ = pc ? __high2float(gn2) : __low2float(gn2);
                            float hr = acc[mi][ni][h * 2 + pc] + bh[0][ni][pc];
                            float hz = acc[mi][ni + 2][h * 2 + pc] + bh[1][ni][pc];
                            float hn = acc[mi][ni + 4][h * 2 + pc] + bh[2][ni][pc];
                            float r = sigmoid_fma(ir + hr);
                            float zz = sigmoid_fma(iz + hz);
                            float nn = tanh_fma(fmaf(r, hn, in_));
                            float hold = hreg[mi][h][ni][pc];
                            float hnew = fmaf(zz, hold - nn, nn);
                            hreg[mi][h][ni][pc] = hnew;
                            hn01[pc] = hnew;
                        }
                        *(__half2*)&Hw[(size_t)(m0 + rl) * 512 + dd] =
                            __floats2half2_rn(hn01[0], hn01[1]);
                        if (t == NSTEPS - 1) {
                            *(float2*)&Hout[(size_t)(m0 + rl) * 512 + dd] =
                                make_float2(hn01[0], hn01[1]);
                        }
                    }
                }
            }
        }

        // ---- publish own H slice (release, cumulative over __syncthreads)
        __syncthreads();
        if (tid == 0) {
            asm volatile("red.release.gpu.global.add.u32 [%0], %1;"
                         :: "l"(flagbase + db), "r"(1u) : "memory");
        }
    }
#undef LOADA
#undef WAITF
}

// ---------------- kernel: prediction head + seq_last add ----------------
__global__ void head_kernel(const float* __restrict__ Wps, const float* __restrict__ bps,
                            const float* __restrict__ Wpt, const float* __restrict__ bpt,
                            float* __restrict__ out) {
    int n = blockIdx.x;
    int lane = threadIdx.x & 31, w = threadIdx.x >> 5;   // 4 warps
    const float* hs = g_Hs + (size_t)n * DM;
    const float* ht = g_Ht + (size_t)n * DM;
    #pragma unroll
    for (int pp = 0; pp < 4; pp++) {
        int p = w * 4 + pp;
        float acc = 0.f;
        for (int k = lane; k < DM; k += 32)
            acc = fmaf(hs[k], Wps[p * DM + k], fmaf(ht[k], Wpt[p * DM + k], acc));
        #pragma unroll
        for (int o = 16; o; o >>= 1) acc += __shfl_xor_sync(0xffffffffu, acc, o);
        if (lane == 0) {
            int b = n >> 5, c = n & 31;
            out[b * (16 * 32) + p * 32 + c] = acc + bps[p] + bpt[p] + g_seq_last[n];
        }
    }
}

// ---------------- launch ----------------
extern "C" void kernel_launch(void* const* d_in, const int* in_sizes, int n_in,
                              void* d_out, int out_size) {
    const float* x     = (const float*)d_in[0];
    const float* W_emb = (const float*)d_in[1];
    const float* b_emb = (const float*)d_in[2];
    const float* Wih_s = (const float*)d_in[3];
    const float* Whh_s = (const float*)d_in[4];
    const float* bih_s = (const float*)d_in[5];
    const float* bhh_s = (const float*)d_in[6];
    const float* Wih_t = (const float*)d_in[7];
    const float* Whh_t = (const float*)d_in[8];
    const float* bih_t = (const float*)d_in[9];
    const float* bhh_t = (const float*)d_in[10];
    const float* pos_s = (const float*)d_in[11];
    const float* ch_s  = (const float*)d_in[12];
    const float* pos_t = (const float*)d_in[13];
    const float* ch_t  = (const float*)d_in[14];
    const float* Wps   = (const float*)d_in[15];
    const float* bps   = (const float*)d_in[16];
    const float* Wpt   = (const float*)d_in[17];
    const float* bpt   = (const float*)d_in[18];
    float* out = (float*)d_out;

    cudaFuncSetAttribute(scan_kernel, cudaFuncAttributeMaxDynamicSharedMemorySize, SCAN_SMEM);

    cvt_weights<<<(TD * DM + 255) / 256, 256>>>(Wih_s, Whh_s, Wih_t, Whh_t);
    preproc<<<(BBATCH * LL) / 8, 256>>>(x);
    embed<<<dim3((NR * SXN) / 8, 2), 256>>>(W_emb, b_emb);
    build_pe<<<(NR * DM + 255) / 256, 256>>>(pos_s, ch_s, pos_t, ch_t);
    init_state<<<(NR * DM + 255) / 256, 256>>>();

    // Gi for all 64 scan steps (M = 65536) and decoder step (M = 1024)
    gemm_gi<<<dim3(TD / BN, (NR * SXN) / BM, 2), 256>>>(0, bih_s, bih_t);
    gemm_gi<<<dim3(TD / BN, NR / BM, 2), 256>>>(1, bih_s, bih_t);

    // fused persistent scan: 64 steps + decoder step, one launch
    scan_kernel<<<SCAN_CTAS, 512, SCAN_SMEM>>>(bhh_s, bhh_t);

    head_kernel<<<NR, 128>>>(Wps, bps, Wpt, bpt, out);
}

// round 17
// speedup vs baseline: 1.8695x; 1.2518x over previous
#include <cuda_runtime.h>
#include <cuda_fp16.h>
#include <cstdint>
#include <cstddef>

// ---------------- problem constants ----------------
#define BBATCH 32
#define LL   1024
#define DM   512
#define TD   1536          // 3*D
#define NR   1024          // B*C
#define SXN  64
#define SEGN 16
#define NSTEPS 65          // 64 scan steps + 1 decoder step
#define SCAN_CTAS 128
static constexpr size_t SLAB = (size_t)NR * TD;

// ---------------- device scratch ----------------
__device__ float g_seq_last[NR];
__device__ float g_xs[(size_t)NR * LL];
__device__ float g_xt[(size_t)NR * LL];
__device__ __half g_Es[(size_t)NR * SXN * DM];
__device__ __half g_Et[(size_t)NR * SXN * DM];
__device__ __half g_pes[(size_t)NR * DM];
__device__ __half g_pet[(size_t)NR * DM];
__device__ __half g_Wih_s[(size_t)TD * DM];
__device__ __half g_Whh_s[(size_t)TD * DM];
__device__ __half g_Wih_t[(size_t)TD * DM];
__device__ __half g_Whh_t[(size_t)TD * DM];
__device__ __half g_Gi_s[(size_t)NSTEPS * NR * TD];  // fp16 preacts (bih folded)
__device__ __half g_Gi_t[(size_t)NSTEPS * NR * TD];
__device__ __half g_Hbuf[2][2][(size_t)NR * DM];     // [stream][pingpong]
__device__ float g_Hs[(size_t)NR * DM];
__device__ float g_Ht[(size_t)NR * DM];
__device__ unsigned g_barriers[16];                  // per (z, mb) group

// ---------------- helpers ----------------
__device__ __forceinline__ uint32_t smem_u32(const void* p) {
    uint32_t r;
    asm volatile("{ .reg .u64 t; cvta.to.shared.u64 t, %1; cvt.u32.u64 %0, t; }"
                 : "=r"(r) : "l"(p));
    return r;
}

__device__ __forceinline__ void mma16816(float* c, const uint32_t* a, const uint32_t* b) {
    asm volatile(
        "mma.sync.aligned.m16n8k16.row.col.f32.f16.f16.f32 "
        "{%0,%1,%2,%3}, {%4,%5,%6,%7}, {%8,%9}, {%0,%1,%2,%3};\n"
        : "+f"(c[0]), "+f"(c[1]), "+f"(c[2]), "+f"(c[3])
        : "r"(a[0]), "r"(a[1]), "r"(a[2]), "r"(a[3]), "r"(b[0]), "r"(b[1]));
}

#define SWZ(o) ((o) ^ (((o) >> 3) & 0x70))

// FMA-only 2^v for v in [-31, 31]; err ~1e-7 rel
__device__ __forceinline__ float exp2_fma(float v) {
    float k = v + 12582912.0f;
    float n = k - 12582912.0f;
    float f = v - n;
    int ni = __float_as_int(k) - 0x4B400000;
    float p = 1.54035304e-4f;
    p = fmaf(p, f, 1.33335581e-3f);
    p = fmaf(p, f, 9.61812911e-3f);
    p = fmaf(p, f, 5.55041087e-2f);
    p = fmaf(p, f, 2.40226507e-1f);
    p = fmaf(p, f, 6.93147180e-1f);
    p = fmaf(p, f, 1.0f);
    return __int_as_float(__float_as_int(p) + (ni << 23));
}

// FMA-only reciprocal, 2 Newton steps; err ~1.3e-6 rel
__device__ __forceinline__ float rcp_nr(float d) {
    float x = __int_as_float(0x7EF311C3 - __float_as_int(d));
    x = x * fmaf(-d, x, 2.0f);
    x = x * fmaf(-d, x, 2.0f);
    return x;
}

__device__ __forceinline__ float sigmoid_fma(float x) {
    float v = fmaxf(fminf(-x * 1.44269504f, 30.f), -30.f);
    return rcp_nr(1.0f + exp2_fma(v));
}

__device__ __forceinline__ float tanh_fma(float x) {
    float v = fmaxf(fminf(-x * 2.88539008f, 30.f), -30.f);
    float s = rcp_nr(1.0f + exp2_fma(v));
    return fmaf(2.0f, s, -1.0f);
}

// ---------------- kernel: weight fp32 -> fp16 ----------------
__global__ void cvt_weights(const float* __restrict__ wih_s, const float* __restrict__ whh_s,
                            const float* __restrict__ wih_t, const float* __restrict__ whh_t) {
    int i = blockIdx.x * blockDim.x + threadIdx.x;
    if (i >= TD * DM) return;
    g_Wih_s[i] = __float2half(wih_s[i]);
    g_Whh_s[i] = __float2half(whh_s[i]);
    g_Wih_t[i] = __float2half(wih_t[i]);
    g_Whh_t[i] = __float2half(whh_t[i]);
}

// ---------------- kernel: preprocess (moving mean over CHANNELS) -------------
__global__ void preproc(const float* __restrict__ x) {
    int idx = blockIdx.x * (blockDim.x >> 5) + (threadIdx.x >> 5);  // b*1024 + l
    int lane = threadIdx.x & 31;
    if (idx >= BBATCH * LL) return;
    int b = idx >> 10, l = idx & 1023;
    const float* xb = x + (size_t)b * LL * 32;
    float last = xb[(LL - 1) * 32 + lane];
    float v = xb[(size_t)l * 32 + lane] - last;
    float s = 0.f;
    #pragma unroll
    for (int j = -12; j <= 12; j++) {
        int c = lane + j;
        c = c < 0 ? 0 : (c > 31 ? 31 : c);
        s += __shfl_sync(0xffffffffu, v, c);
    }
    float mean = s * (1.0f / 25.0f);
    int n = (b << 5) + lane;
    g_xt[(size_t)n * LL + l] = mean;
    g_xs[(size_t)n * LL + l] = v - mean;
    if (l == LL - 1) g_seq_last[n] = last;
}

// ---------------- kernel: value embedding (K=16 GEMM + ReLU) ------------------
__global__ void embed(const float* __restrict__ W_emb, const float* __restrict__ b_emb) {
    __shared__ float sWT[SEGN * DM];
    __shared__ float sb[DM];
    const float* src = blockIdx.y ? g_xt : g_xs;
    __half* dst = blockIdx.y ? g_Et : g_Es;
    for (int i = threadIdx.x; i < SEGN * DM; i += blockDim.x) {
        int d = i >> 4, k = i & 15;
        sWT[k * DM + d] = W_emb[i];
    }
    for (int i = threadIdx.x; i < DM; i += blockDim.x) sb[i] = b_emb[i];
    __syncthreads();
    int row0 = blockIdx.x * 8;
    for (int rr = 0; rr < 8; rr++) {
        int r = row0 + rr;
        int sx = r >> 10, n = r & 1023;
        const float* s16 = src + (size_t)n * LL + sx * SEGN;
        float seg[SEGN];
        #pragma unroll
        for (int k = 0; k < SEGN; k++) seg[k] = __ldg(&s16[k]);
        for (int d = threadIdx.x; d < DM; d += blockDim.x) {
            float acc = sb[d];
            #pragma unroll
            for (int k = 0; k < SEGN; k++) acc = fmaf(seg[k], sWT[k * DM + d], acc);
            dst[(size_t)r * DM + d] = __float2half(fmaxf(acc, 0.f));
        }
    }
}

// ---------------- kernel: decoder positional/channel embedding ----------------
__global__ void build_pe(const float* __restrict__ pos_s, const float* __restrict__ ch_s,
                         const float* __restrict__ pos_t, const float* __restrict__ ch_t) {
    int i = blockIdx.x * blockDim.x + threadIdx.x;
    if (i >= NR * DM) return;
    int n = i >> 9, d = i & 511;
    int c = n & 31;
    float vs = (d < 256) ? pos_s[d] : ch_s[c * 256 + (d - 256)];
    float vt = (d < 256) ? pos_t[d] : ch_t[c * 256 + (d - 256)];
    g_pes[i] = __float2half(vs);
    g_pet[i] = __float2half(vt);
}

// ---------------- kernel: init (H ping buffer 0 + barriers) ----------------
__global__ void init_state() {
    int i = blockIdx.x * blockDim.x + threadIdx.x;
    if (i < 16) g_barriers[i] = 0;
    if (i >= NR * DM) return;
    g_Hbuf[0][0][i] = __float2half(0.f);
    g_Hbuf[1][0][i] = __float2half(0.f);
}

// ---------------- Gi GEMM: C[m][n] = E[m]@Wih[n] + bih[n], fp16 out -----------
// BM=256 x BN=128 tiles, 512 threads (4m x 4n warps, 64x32 per warp).
// B fragments reused by 4 m-warps (was 2) -> half the B-ldmatrix per MMA,
// 4 warps/SMSP for issue-latency hiding. K-loop order identical to the
// 128x128 version -> bitwise-identical output.
#define BM 256
#define BN 128
#define BK 32
#define SST 40
#define GI_SMEM (2 * BM * SST * 2 + 2 * BN * SST * 2)   // 40960 + 20480 = 61440 B

__global__ void __launch_bounds__(512, 1) gemm_gi(int which,
                                                  const float* __restrict__ bias0,
                                                  const float* __restrict__ bias1) {
    extern __shared__ __align__(16) __half gsm[];
    __half (*sA)[BM][SST] = (__half (*)[BM][SST])gsm;                 // [2][256][40]
    __half (*sB)[BN][SST] = (__half (*)[BN][SST])(gsm + 2 * BM * SST); // [2][128][40]

    const __half *A, *W;
    __half* C;
    int z = blockIdx.z;
    if (which == 0) {
        A = z ? g_Et : g_Es;
        W = z ? g_Wih_t : g_Wih_s;
        C = z ? g_Gi_t : g_Gi_s;
    } else {
        A = z ? g_pet : g_pes;
        W = z ? g_Wih_t : g_Wih_s;
        C = (z ? g_Gi_t : g_Gi_s) + (size_t)64 * SLAB;
    }
    const float* bias = z ? bias1 : bias0;

    int tid = threadIdx.x;
    int m0 = blockIdx.y * BM;
    int n0 = blockIdx.x * BN;
    const __half* Ag = A + (size_t)m0 * DM;
    const __half* Wg = W + (size_t)n0 * DM;

    int warp = tid >> 5, lane = tid & 31;
    int wm = warp & 3, wn = warp >> 2;        // 4 x 4 warp grid
    int mwarp = wm * 64, nwarp = wn * 32;

    float acc[4][4][4];
    #pragma unroll
    for (int mi = 0; mi < 4; mi++)
        #pragma unroll
        for (int ni = 0; ni < 4; ni++)
            #pragma unroll
            for (int q = 0; q < 4; q++) acc[mi][ni][q] = 0.f;

    const int KT = DM / BK;   // 16

#define LOAD_TILE(buf, k0) do {                                                       \
        _Pragma("unroll")                                                             \
        for (int i_ = 0; i_ < 2; i_++) {                                              \
            int id_ = tid + 512 * i_;              /* 1024 A chunks */                \
            int r_ = id_ >> 2, c8_ = (id_ & 3) * 8;                                   \
            uint32_t s_ = smem_u32(&sA[buf][r_][c8_]);                                \
            const __half* p_ = Ag + (size_t)r_ * DM + (k0) + c8_;                     \
            asm volatile("cp.async.cg.shared.global [%0], [%1], 16;\n" :: "r"(s_), "l"(p_)); \
        }                                                                             \
        {                                                                             \
            int r_ = tid >> 2, c8_ = (tid & 3) * 8; /* 512 B chunks */                \
            uint32_t s_ = smem_u32(&sB[buf][r_][c8_]);                                \
            const __half* p_ = Wg + (size_t)r_ * DM + (k0) + c8_;                     \
            asm volatile("cp.async.cg.shared.global [%0], [%1], 16;\n" :: "r"(s_), "l"(p_)); \
        }                                                                             \
        asm volatile("cp.async.commit_group;\n" ::: "memory");                        \
    } while (0)

    LOAD_TILE(0, 0);

    for (int kt = 0; kt < KT; kt++) {
        asm volatile("cp.async.wait_group 0;\n" ::: "memory");
        __syncthreads();
        if (kt + 1 < KT) {
            LOAD_TILE((kt + 1) & 1, (kt + 1) * BK);
        }
        int buf = kt & 1;
        #pragma unroll
        for (int ks = 0; ks < 2; ks++) {
            int k16 = ks * 16;
            uint32_t a[4][4];
            #pragma unroll
            for (int mi = 0; mi < 4; mi++) {
                int row = mwarp + mi * 16 + (lane & 15);
                int col = k16 + (lane >> 4) * 8;
                uint32_t addr = smem_u32(&sA[buf][row][col]);
                asm volatile("ldmatrix.sync.aligned.m8n8.x4.shared.b16 {%0,%1,%2,%3}, [%4];\n"
                             : "=r"(a[mi][0]), "=r"(a[mi][1]), "=r"(a[mi][2]), "=r"(a[mi][3])
                             : "r"(addr));
            }
            uint32_t b[4][2];
            #pragma unroll
            for (int nb = 0; nb < 2; nb++) {
                int g = lane >> 3, rr = lane & 7;
                int nrow = nwarp + nb * 16 + ((g >> 1) << 3) + rr;
                int col = k16 + ((g & 1) << 3);
                uint32_t addr = smem_u32(&sB[buf][nrow][col]);
                uint32_t r0, r1, r2, r3;
                asm volatile("ldmatrix.sync.aligned.m8n8.x4.shared.b16 {%0,%1,%2,%3}, [%4];\n"
                             : "=r"(r0), "=r"(r1), "=r"(r2), "=r"(r3) : "r"(addr));
                b[nb * 2][0] = r0;     b[nb * 2][1] = r1;
                b[nb * 2 + 1][0] = r2; b[nb * 2 + 1][1] = r3;
            }
            #pragma unroll
            for (int mi = 0; mi < 4; mi++)
                #pragma unroll
                for (int ni = 0; ni < 4; ni++)
                    mma16816(acc[mi][ni], a[mi], b[ni]);
        }
    }

    #pragma unroll
    for (int mi = 0; mi < 4; mi++) {
        int row = m0 + mwarp + mi * 16 + (lane >> 2);
        #pragma unroll
        for (int ni = 0; ni < 4; ni++) {
            int col = n0 + nwarp + ni * 8 + (lane & 3) * 2;
            float bv0 = bias[col], bv1 = bias[col + 1];
            *(__half2*)&C[(size_t)row * TD + col] =
                __floats2half2_rn(acc[mi][ni][0] + bv0, acc[mi][ni][1] + bv1);
            *(__half2*)&C[(size_t)(row + 8) * TD + col] =
                __floats2half2_rn(acc[mi][ni][2] + bv0, acc[mi][ni][3] + bv1);
        }
    }
#undef LOAD_TILE
}

// ---------------- persistent fused GRU scan (R8 group-barrier version) --------
// 128 CTAs x 512 threads. CTA (z, mb, db): stream z, m [mb*128,+128),
// d [db*64,+64) over 3 gates. Whh slice chunk-major SW128 in smem (196.6KB),
// A triple-buffered (3x10KB), h in registers. 16 warps: 4m x 4n.
// (z, mb) groups of 8 CTAs are independent chains -> per-group barriers.
#define SCAN_SMEM 229440

__global__ void __launch_bounds__(512, 1) scan_kernel(const float* __restrict__ bhh_s,
                                                      const float* __restrict__ bhh_t) {
    extern __shared__ __align__(16) char smraw[];
    uint32_t sbase = smem_u32(smraw);
    uint32_t s0 = (sbase + 1023) & ~1023u;
    const uint32_t sW = s0;                   // 8 chunks x 24576 B (SW128)
    const uint32_t sA = s0 + 196608;          // 3 x 10240 B (128 rows x 80B)
    float* sBias = (float*)(smraw + (s0 + 196608 + 30720 - sbase));

    const int tid = threadIdx.x;
    const int cta = blockIdx.x;
    const int z = cta >> 6;
    const int mb = (cta >> 3) & 7;
    const int db = cta & 7;
    const int m0 = mb * 128;
    const int grp = cta >> 3;
    const int warp = tid >> 5, lane = tid & 31;
    const int wm = warp & 3, wn = warp >> 2;   // 4m x 4n warps: 32m x 48n tiles

    const __half* Whh = z ? g_Whh_t : g_Whh_s;
    const float* bhh = z ? bhh_t : bhh_s;
    const __half* Gi = z ? g_Gi_t : g_Gi_s;
    __half* Hb0 = g_Hbuf[z][0];
    __half* Hb1 = g_Hbuf[z][1];
    float* Hout = z ? g_Ht : g_Hs;

    // ---- resident weight slice, chunk-major SW128
    for (int idx = tid; idx < 12288; idx += 512) {
        int c = idx / 1536;
        int rem = idx - c * 1536;
        int j = rem >> 3, w = rem & 7;
        int jm = j % 48;
        int grow = (jm >> 4) * 512 + db * 64 + (j / 48) * 16 + (jm & 15);
        uint32_t off = (uint32_t)(j * 128 + w * 16);
        uint32_t dst = sW + c * 24576 + SWZ(off);
        const __half* src = Whh + (size_t)grow * 512 + c * 64 + w * 8;
        asm volatile("cp.async.cg.shared.global [%0], [%1], 16;\n" :: "r"(dst), "l"(src));
    }
    asm volatile("cp.async.commit_group;\ncp.async.wait_group 0;\n" ::: "memory");
    if (tid < 192) sBias[tid] = bhh[(tid >> 6) * 512 + db * 64 + (tid & 63)];
    __syncthreads();

    // ---- per-thread bhh preload: bh[gate][ni][pc]
    float bh[3][2][2];
    #pragma unroll
    for (int g = 0; g < 3; g++)
        #pragma unroll
        for (int ni = 0; ni < 2; ni++)
            #pragma unroll
            for (int pc = 0; pc < 2; pc++) {
                int dd = db * 64 + wn * 16 + ni * 8 + (lane & 3) * 2 + pc;
                bh[g][ni][pc] = bhh[g * 512 + dd];
            }

    // ---- register-resident h (16 elements per thread)
    float hreg[2][2][2][2];
    #pragma unroll
    for (int mi = 0; mi < 2; mi++)
        #pragma unroll
        for (int h = 0; h < 2; h++)
            #pragma unroll
            for (int ni = 0; ni < 2; ni++) { hreg[mi][h][ni][0] = 0.f; hreg[mi][h][ni][1] = 0.f; }

#define LOADA(buf, k0) do {                                                          \
        int r_ = tid >> 2, co_ = tid & 3;                                            \
        uint32_t s_ = sA + (buf) * 10240 + r_ * 80 + co_ * 16;                       \
        const __half* p_ = Ag + (size_t)r_ * 512 + (k0) + co_ * 8;                   \
        asm volatile("cp.async.cg.shared.global [%0], [%1], 16;\n" :: "r"(s_), "l"(p_)); \
        asm volatile("cp.async.commit_group;\n" ::: "memory");                       \
    } while (0)

    for (int t = 0; t < NSTEPS; t++) {
        // ---- prefetch this step's Gi block into L2
        {
            const __half* gib = Gi + (size_t)(t * 1024 + m0) * 1536 + db * 64;
            if (tid < 384) {
                int row = tid & 127, gate = tid >> 7;
                const __half* pf = gib + (size_t)row * 1536 + gate * 512;
                asm volatile("prefetch.global.L2 [%0];" :: "l"(pf));
            }
        }

        float acc[2][6][4];
        #pragma unroll
        for (int mi = 0; mi < 2; mi++)
            #pragma unroll
            for (int ni = 0; ni < 6; ni++)
                #pragma unroll
                for (int q = 0; q < 4; q++) acc[mi][ni][q] = 0.f;

        if (t > 0) {
            const __half* Ag = ((t & 1) ? Hb1 : Hb0) + (size_t)m0 * 512;
            LOADA(0, 0);
            LOADA(1, 32);
            for (int kt = 0; kt < 16; kt++) {
                if (kt < 15) asm volatile("cp.async.wait_group 1;\n" ::: "memory");
                else         asm volatile("cp.async.wait_group 0;\n" ::: "memory");
                __syncthreads();
                if (kt + 2 < 16) LOADA((kt + 2) % 3, (kt + 2) * 32);
                int buf = kt % 3;
                #pragma unroll
                for (int ks = 0; ks < 2; ks++) {
                    uint32_t a[2][4];
                    #pragma unroll
                    for (int mi = 0; mi < 2; mi++) {
                        int row = wm * 32 + mi * 16 + (lane & 15);
                        uint32_t addr = sA + buf * 10240 + row * 80
                                        + (ks * 16 + (lane >> 4) * 8) * 2;
                        asm volatile("ldmatrix.sync.aligned.m8n8.x4.shared.b16 {%0,%1,%2,%3}, [%4];\n"
                                     : "=r"(a[mi][0]), "=r"(a[mi][1]), "=r"(a[mi][2]), "=r"(a[mi][3])
                                     : "r"(addr));
                    }
                    uint32_t b[6][2];
                    #pragma unroll
                    for (int nb = 0; nb < 3; nb++) {
                        int g = lane >> 3, rr = lane & 7;
                        int j = wn * 48 + nb * 16 + ((g >> 1) << 3) + rr;
                        uint32_t off = (uint32_t)(j * 128 + (kt & 1) * 64 + ks * 32 + (g & 1) * 16);
                        uint32_t addr = sW + (kt >> 1) * 24576 + SWZ(off);
                        uint32_t r0, r1, r2, r3;
                        asm volatile("ldmatrix.sync.aligned.m8n8.x4.shared.b16 {%0,%1,%2,%3}, [%4];\n"
                                     : "=r"(r0), "=r"(r1), "=r"(r2), "=r"(r3) : "r"(addr));
                        b[nb * 2][0] = r0;     b[nb * 2][1] = r1;
                        b[nb * 2 + 1][0] = r2; b[nb * 2 + 1][1] = r3;
                    }
                    #pragma unroll
                    for (int mi = 0; mi < 2; mi++)
                        #pragma unroll
                        for (int ni = 0; ni < 6; ni++)
                            mma16816(acc[mi][ni], a[mi], b[ni]);
                }
            }
        }

        // ---- gate phase (registers)
        {
            const __half* gib = Gi + (size_t)(t * 1024 + m0) * 1536;
            __half* Hw = ((t + 1) & 1) ? Hb1 : Hb0;
            int ddb = db * 64 + wn * 16 + (lane & 3) * 2;
            #pragma unroll
            for (int mi = 0; mi < 2; mi++) {
                #pragma unroll
                for (int h = 0; h < 2; h++) {
                    int rl = wm * 32 + mi * 16 + (lane >> 2) + h * 8;
                    #pragma unroll
                    for (int ni = 0; ni < 2; ni++) {
                        int dd = ddb + ni * 8;
                        const __half* gp = gib + (size_t)rl * 1536 + dd;
                        __half2 gr2 = *(const __half2*)(gp);
                        __half2 gz2 = *(const __half2*)(gp + 512);
                        __half2 gn2 = *(const __half2*)(gp + 1024);
                        float hn01[2];
                        #pragma unroll
                        for (int pc = 0; pc < 2; pc++) {
                            float ir = pc ? __high2float(gr2) : __low2float(gr2);
                            float iz = pc ? __high2float(gz2) : __low2float(gz2);
                            float in_ = pc ? __high2float(gn2) : __low2float(gn2);
                            float hr = acc[mi][ni][h * 2 + pc] + bh[0][ni][pc];
                            float hz = acc[mi][ni + 2][h * 2 + pc] + bh[1][ni][pc];
                            float hn = acc[mi][ni + 4][h * 2 + pc] + bh[2][ni][pc];
                            float r = sigmoid_fma(ir + hr);
                            float zz = sigmoid_fma(iz + hz);
                            float nn = tanh_fma(fmaf(r, hn, in_));
                            float hold = hreg[mi][h][ni][pc];
                            float hnew = fmaf(zz, hold - nn, nn);
                            hreg[mi][h][ni][pc] = hnew;
                            hn01[pc] = hnew;
                        }
                        *(__half2*)&Hw[(size_t)(m0 + rl) * 512 + dd] =
                            __floats2half2_rn(hn01[0], hn01[1]);
                        if (t == NSTEPS - 1) {
                            *(float2*)&Hout[(size_t)(m0 + rl) * 512 + dd] =
                                make_float2(hn01[0], hn01[1]);
                        }
                    }
                }
            }
        }

        // ---- per-group barrier (8 CTAs of (z, mb))
        __syncthreads();
        if (tid == 0) {
            __threadfence();
            atomicAdd(&g_barriers[grp], 1u);
            unsigned need = (unsigned)(t + 1) * 8u;
            unsigned v;
            do {
                asm volatile("ld.global.acquire.gpu.u32 %0, [%1];"
                             : "=r"(v) : "l"(&g_barriers[grp]));
            } while (v < need);
        }
        __syncthreads();
    }
#undef LOADA
}

// ---------------- kernel: prediction head + seq_last add ----------------
__global__ void head_kernel(const float* __restrict__ Wps, const float* __restrict__ bps,
                            const float* __restrict__ Wpt, const float* __restrict__ bpt,
                            float* __restrict__ out) {
    int n = blockIdx.x;
    int lane = threadIdx.x & 31, w = threadIdx.x >> 5;   // 4 warps
    const float* hs = g_Hs + (size_t)n * DM;
    const float* ht = g_Ht + (size_t)n * DM;
    #pragma unroll
    for (int pp = 0; pp < 4; pp++) {
        int p = w * 4 + pp;
        float acc = 0.f;
        for (int k = lane; k < DM; k += 32)
            acc = fmaf(hs[k], Wps[p * DM + k], fmaf(ht[k], Wpt[p * DM + k], acc));
        #pragma unroll
        for (int o = 16; o; o >>= 1) acc += __shfl_xor_sync(0xffffffffu, acc, o);
        if (lane == 0) {
            int b = n >> 5, c = n & 31;
            out[b * (16 * 32) + p * 32 + c] = acc + bps[p] + bpt[p] + g_seq_last[n];
        }
    }
}

// ---------------- launch ----------------
extern "C" void kernel_launch(void* const* d_in, const int* in_sizes, int n_in,
                              void* d_out, int out_size) {
    const float* x     = (const float*)d_in[0];
    const float* W_emb = (const float*)d_in[1];
    const float* b_emb = (const float*)d_in[2];
    const float* Wih_s = (const float*)d_in[3];
    const float* Whh_s = (const float*)d_in[4];
    const float* bih_s = (const float*)d_in[5];
    const float* bhh_s = (const float*)d_in[6];
    const float* Wih_t = (const float*)d_in[7];
    const float* Whh_t = (const float*)d_in[8];
    const float* bih_t = (const float*)d_in[9];
    const float* bhh_t = (const float*)d_in[10];
    const float* pos_s = (const float*)d_in[11];
    const float* ch_s  = (const float*)d_in[12];
    const float* pos_t = (const float*)d_in[13];
    const float* ch_t  = (const float*)d_in[14];
    const float* Wps   = (const float*)d_in[15];
    const float* bps   = (const float*)d_in[16];
    const float* Wpt   = (const float*)d_in[17];
    const float* bpt   = (const float*)d_in[18];
    float* out = (float*)d_out;

    cudaFuncSetAttribute(scan_kernel, cudaFuncAttributeMaxDynamicSharedMemorySize, SCAN_SMEM);
    cudaFuncSetAttribute(gemm_gi, cudaFuncAttributeMaxDynamicSharedMemorySize, GI_SMEM);

    cvt_weights<<<(TD * DM + 255) / 256, 256>>>(Wih_s, Whh_s, Wih_t, Whh_t);
    preproc<<<(BBATCH * LL) / 8, 256>>>(x);
    embed<<<dim3((NR * SXN) / 8, 2), 256>>>(W_emb, b_emb);
    build_pe<<<(NR * DM + 255) / 256, 256>>>(pos_s, ch_s, pos_t, ch_t);
    init_state<<<(NR * DM + 255) / 256, 256>>>();

    // Gi for all 64 scan steps (M = 65536) and decoder step (M = 1024)
    gemm_gi<<<dim3(TD / BN, (NR * SXN) / BM, 2), 512, GI_SMEM>>>(0, bih_s, bih_t);
    gemm_gi<<<dim3(TD / BN, NR / BM, 2), 512, GI_SMEM>>>(1, bih_s, bih_t);

    // fused persistent scan: 64 steps + decoder step, one launch
    scan_kernel<<<SCAN_CTAS, 512, SCAN_SMEM>>>(bhh_s, bhh_t);

    head_kernel<<<NR, 128>>>(Wps, bps, Wpt, bpt, out);
}